// round 12
// baseline (speedup 1.0000x reference)
#include <cuda_runtime.h>

// ---------------- problem constants ----------------
#define NXg 256
#define NYg 256
#define NG  (NXg*NYg)

// tile: interior 16(x) x 32(y), halo 4 -> ext 24x40; strips of 2 in y
#define IXt 16
#define IYt 32
#define Hh  4
#define EXt 24
#define EYt 40
#define EXT (EXt*EYt)      // 960
#define SW   2
#define NSTR (EYt/SW)      // 20
#define NSTRIPS (EXt*NSTR) // 480
#define NT   512
#define NBX (NYg/IYt)      // 8
#define NBY (NXg/IXt)      // 16
#define NCTA (NBX*NBY)     // 128 CTAs <= 148 SMs -> co-resident
#define RELAX  100
#define TSTEPS 1024
#define NSTEPS (RELAX + TSTEPS)

// ---------------- device state ----------------
__device__ float g_m[2][3*NG];   // ping-pong exchange state
__device__ unsigned g_count;     // MONOTONIC arrival counter (reset at kernel start)
__device__ unsigned g_ibar;      // init barrier counter (self-resetting)
__device__ unsigned g_isense;    // init barrier sense (2 flips/run -> replay-safe)

// init-only sense-reversing barrier (used exactly twice per run)
__device__ __forceinline__ void initbar(unsigned& lsense)
{
    __syncthreads();
    if (threadIdx.x == 0) {
        unsigned s = lsense ^ 1u;
        lsense = s;
        unsigned old;
        asm volatile("atom.add.acq_rel.gpu.u32 %0, [%1], 1;"
                     : "=r"(old) : "l"(&g_ibar) : "memory");
        if (old == NCTA - 1u) {
            asm volatile("st.relaxed.gpu.u32 [%0], %1;" :: "l"(&g_ibar), "r"(0u) : "memory");
            asm volatile("st.release.gpu.u32 [%0], %1;" :: "l"(&g_isense), "r"(s) : "memory");
        } else {
            unsigned v;
            do {
                asm volatile("ld.acquire.gpu.u32 %0, [%1];" : "=r"(v) : "l"(&g_isense) : "memory");
            } while (v != s);
        }
    }
    __syncthreads();
}

// max RK substage (1..4) at which a strip must still be computed; -1 = dead.
__device__ __forceinline__ int strip_cap(int ex, int sy, int gx0, int gy0)
{
    int gx = gx0 + ex;
    int cap = -1;
    #pragma unroll
    for (int j = 0; j < SW; j++) {
        int ey = SW*sy + j;
        int gy = gy0 + ey;
        if (gx < 0 || gx >= NXg || gy < 0 || gy >= NYg) continue;
        int c = 99;
        if (gx0 >= 0)         c = min(c, ex);
        if (gx0 + EXt <= NXg) c = min(c, EXt - 1 - ex);
        if (gy0 >= 0)         c = min(c, ey);
        if (gy0 + EYt <= NYg) c = min(c, EYt - 1 - ey);
        cap = max(cap, min(c, 4));
    }
    return cap;
}

__global__ void __launch_bounds__(NT, 1)
k_sim(const float* __restrict__ sig,  const float* __restrict__ Bext,
      const float* __restrict__ Msat, const float* __restrict__ src,
      const float* __restrict__ pmask, float* __restrict__ out)
{
    __shared__ __align__(16) float4 SA[EXT];   // (mx,my,mz,pad) per cell
    __shared__ __align__(16) float4 SB[EXT];
    __shared__ float red[NT/32];
    __shared__ float s_pminv;
    __shared__ float s_sig[TSTEPS];
    __shared__ signed char sClass[NSTRIPS];
    __shared__ short sOwner[NSTRIPS];

    const int tid = threadIdx.x;
    const int gx0 = (int)blockIdx.y * IXt - Hh;
    const int gy0 = (int)blockIdx.x * IYt - Hh;
    const bool cta0 = (blockIdx.x == 0 && blockIdx.y == 0);

    // ---- deterministic cap-ordered thread->strip mapping ----
    if (tid < NSTRIPS) {
        sClass[tid] = (signed char)strip_cap(tid / NSTR, tid % NSTR, gx0, gy0);
        sOwner[tid] = -1;
    }
    __syncthreads();
    if (tid < NSTRIPS && sClass[tid] >= 0) {
        int myc = sClass[tid];
        int r = 0;
        for (int s = 0; s < NSTRIPS; ++s) {
            int cs = sClass[s];
            r += (cs > myc) || (cs == myc && s < tid);
        }
        sOwner[r] = (short)tid;
    }
    __syncthreads();
    const int myStrip = (tid < NSTRIPS) ? (int)sOwner[tid] : -1;
    const bool live = (myStrip >= 0);
    const int ex  = live ? myStrip / NSTR : 0;
    const int sy  = live ? myStrip % NSTR : 0;
    const int scap = live ? strip_cap(ex, sy, gx0, gy0) : -1;

    const int gx  = gx0 + ex;
    const int gyb = gy0 + SW*sy;
    const int e   = ex*EYt + SW*sy;

    const int gxc = min(max(gx, 0), NXg - 1);
    const int gyc = min(max(gyb, 0), NYg - SW);
    const int g   = gxc*NYg + gyc;

    const int exm = (ex == 0       || gx <= 0)       ? ex : ex - 1;
    const int exq = (ex == EXt - 1 || gx >= NXg - 1) ? ex : ex + 1;
    const int emb = exm*EYt + SW*sy;
    const int epb = exq*EYt + SW*sy;
    const int yL = (sy == 0        || gyb <= 0)                ? e          : e - 1;
    const int yR = (sy == NSTR - 1 || gyb + SW - 1 >= NYg - 1) ? e + SW - 1 : e + SW;

    const bool sint = (scap >= 4);   // interior <=> needed through stage 4
    const bool ring = sint && (ex < Hh + 4 || ex >= Hh + IXt - 4 ||
                               sy < Hh/SW + 2 || sy >= (Hh + IYt)/SW - 2);

    const float MU0f    = (float)(4e-7 * 3.14159265358979323846);
    const float TWO_A   = (float)(2.0 * 3.65e-12);
    const float INV_DX2 = (float)(1.0 / (50e-9 * 50e-9));
    const double hd  = 1.7595e11 * 5e-12;
    const float c05  = (float)(0.5 * hd);
    const float cfl  = (float)hd;
    const float h6   = (float)(hd / 6.0);
    const float i_rx = (float)(1.0 / (1.0 + 0.5 * 0.5));
    const float i_rn = (float)(1.0 / (1.0 + 0.01 * 0.01));
    // folded (negative) coefficients: st = fma(nC, k', mb), k' = p + alpha*q
    const float nC05_rx = -(c05 * i_rx), nCfl_rx = -(cfl * i_rx), nH6_rx = -(h6 * i_rx);
    const float nC05_rn = -(c05 * i_rn), nCfl_rn = -(cfl * i_rn), nH6_rn = -(h6 * i_rn);

    // -------- static per-cell constants (registers, whole run) --------
    float rB0[SW], rB1[SW], rB2[SW], rS0[SW], rS1[SW], rS2[SW];
    float rCL[SW], rDg[SW], pmw[SW], m0x[SW];
    int anyp = 0;
    #pragma unroll
    for (int j = 0; j < SW; j++) {
        int gj = live ? gx*NYg + (gyb + j) : 0;   // live strips are fully in-domain
        float ms = Msat[gj];
        rCL[j] = (TWO_A / ms) * INV_DX2;
        rDg[j] = MU0f * ms;
        rB0[j] = Bext[0*NG + gj]; rB1[j] = Bext[1*NG + gj]; rB2[j] = Bext[2*NG + gj];
        rS0[j] = src [0*NG + gj]; rS1[j] = src [1*NG + gj]; rS2[j] = src [2*NG + gj];
        float pv = sint ? pmask[gj] : 0.f;
        pmw[j] = pv * ms;
        m0x[j] = 0.f;
        if (pv != 0.f) anyp = 1;
    }

    for (int i = tid; i < TSTEPS; i += NT) s_sig[i] = sig[i];
    if (cta0) {
        for (int i = tid; i < TSTEPS; i += NT) out[i] = 0.f;
        if (tid == 0)
            asm volatile("st.relaxed.gpu.u32 [%0], %1;" :: "l"(&g_count), "r"(0u) : "memory");
    }

    const int hasp = __syncthreads_or(anyp);
    if (hasp) {
        float s = 0.f;
        for (int i = tid; i < NG; i += NT) s += pmask[i];
        #pragma unroll
        for (int o = 16; o; o >>= 1) s += __shfl_down_sync(0xffffffffu, s, o);
        if ((tid & 31) == 0) red[tid >> 5] = s;
        __syncthreads();
        if (tid < 32) {
            float v = (tid < NT/32) ? red[tid] : 0.f;
            #pragma unroll
            for (int o = 8; o; o >>= 1) v += __shfl_down_sync(0xffffffffu, v, o);
            if (tid == 0) s_pminv = 1.f / v;
        }
    }

    unsigned lsense = 0;
    initbar(lsense);
    initbar(lsense);

    float mb0[SW], mb1[SW], mb2[SW];
    #pragma unroll
    for (int j = 0; j < SW; j++) { mb0[j] = 0.f; mb1[j] = 0.f; mb2[j] = 1.f; }
    if (live) {
        SA[e]     = make_float4(0.f, 0.f, 1.f, 0.f);
        SA[e + 1] = make_float4(0.f, 0.f, 1.f, 0.f);
    }
    __syncthreads();

    for (int step = 0; step < NSTEPS; ++step) {
        const bool  probe = (step >= RELAX);
        const float sv    = probe ? s_sig[step - RELAX] : 0.f;
        const float alpha = probe ? 0.01f : 0.5f;
        const float nC05  = probe ? nC05_rn : nC05_rx;
        const float nCfl  = probe ? nCfl_rn : nCfl_rx;
        const float nH6   = probe ? nH6_rn  : nH6_rx;
        const float* __restrict__ m_in  = g_m[(step + 1) & 1];
        float*       __restrict__ m_out = g_m[step & 1];

        // ---- halo refresh from L2 ----
        if (live && !sint && step > 0) {
            float2 a = __ldcg((const float2*)&m_in[0*NG + g]);
            float2 b = __ldcg((const float2*)&m_in[1*NG + g]);
            float2 c = __ldcg((const float2*)&m_in[2*NG + g]);
            mb0[0]=a.x; mb0[1]=a.y;
            mb1[0]=b.x; mb1[1]=b.y;
            mb2[0]=c.x; mb2[1]=c.y;
            SA[e]     = make_float4(a.x, b.x, c.x, 0.f);
            SA[e + 1] = make_float4(a.y, b.y, c.y, 0.f);
        }

        float tB0[SW], tB1[SW], tB2[SW];
        float st0[SW], st1[SW], st2[SW];
        float a0[SW], a1[SW], a2[SW];
        #pragma unroll
        for (int j = 0; j < SW; j++) {
            tB0[j] = fmaf(sv, rS0[j], rB0[j]);
            tB1[j] = fmaf(sv, rS1[j], rB1[j]);
            tB2[j] = fmaf(sv, rS2[j], rB2[j]);
            st0[j] = mb0[j]; st1[j] = mb1[j]; st2[j] = mb2[j];
            a0[j] = 0.f; a1[j] = 0.f; a2[j] = 0.f;
        }
        __syncthreads();

        // one RK substage; k' = p + alpha*q (sign & inv1a folded into coefs)
        auto stage = [&](const float4* __restrict__ S,
                         float4* __restrict__ D,
                         float nCoef, float w, bool writeD) {
            float4 xmA = S[emb],  xmB = S[emb + 1];   // x- neighbors (j=0,1)
            float4 xpA = S[epb],  xpB = S[epb + 1];   // x+ neighbors
            float4 ylv = S[yL];                        // y- neighbor of j=0
            float4 yrv = S[yR];                        // y+ neighbor of j=1
            float xm0[SW] = {xmA.x, xmB.x}, xm1[SW] = {xmA.y, xmB.y}, xm2[SW] = {xmA.z, xmB.z};
            float xp0[SW] = {xpA.x, xpB.x}, xp1[SW] = {xpA.y, xpB.y}, xp2[SW] = {xpA.z, xpB.z};
            #pragma unroll
            for (int j = 0; j < SW; j++) {
                float mx = st0[j], my = st1[j], mz = st2[j];
                float yl0 = j ? st0[j-1] : ylv.x;
                float yl1 = j ? st1[j-1] : ylv.y;
                float yl2 = j ? st2[j-1] : ylv.z;
                float yr0 = (j < SW-1) ? st0[j+1] : yrv.x;
                float yr1 = (j < SW-1) ? st1[j+1] : yrv.y;
                float yr2 = (j < SW-1) ? st2[j+1] : yrv.z;
                float l0 = xm0[j] + xp0[j] + yl0 + yr0 - 4.f*mx;
                float l1 = xm1[j] + xp1[j] + yl1 + yr1 - 4.f*my;
                float l2 = xm2[j] + xp2[j] + yl2 + yr2 - 4.f*mz;
                float Bx = fmaf(rCL[j], l0, tB0[j]);
                float By = fmaf(rCL[j], l1, tB1[j]);
                float Bz = fmaf(rCL[j], l2, tB2[j]) - rDg[j]*mz;
                float px = my*Bz - mz*By;
                float py = mz*Bx - mx*Bz;
                float pz = mx*By - my*Bx;
                float qx = my*pz - mz*py;
                float qy = mz*px - mx*pz;
                float qz = mx*py - my*px;
                float k0 = fmaf(alpha, qx, px);
                float k1 = fmaf(alpha, qy, py);
                float k2 = fmaf(alpha, qz, pz);
                a0[j] = fmaf(w, k0, a0[j]);
                a1[j] = fmaf(w, k1, a1[j]);
                a2[j] = fmaf(w, k2, a2[j]);
                st0[j] = fmaf(nCoef, k0, mb0[j]);
                st1[j] = fmaf(nCoef, k1, mb1[j]);
                st2[j] = fmaf(nCoef, k2, mb2[j]);
            }
            if (writeD) {
                D[e]     = make_float4(st0[0], st1[0], st2[0], 0.f);
                D[e + 1] = make_float4(st0[1], st1[1], st2[1], 0.f);
            }
        };

        if (scap >= 1) stage(SA, SB, nC05, 1.f, true);
        __syncthreads();
        if (scap >= 2) stage(SB, SA, nC05, 2.f, true);
        __syncthreads();
        if (scap >= 3) stage(SA, SB, nCfl, 2.f, true);
        __syncthreads();
        if (scap >= 4) stage(SB, SA, 0.f, 1.f, false);   // k4 folded into acc

        // ---- final m (interior): SA publish + exchange ring to L2 ----
        float part = 0.f;
        if (sint) {
            #pragma unroll
            for (int j = 0; j < SW; j++) {
                mb0[j] = fmaf(nH6, a0[j], mb0[j]);
                mb1[j] = fmaf(nH6, a1[j], mb1[j]);
                mb2[j] = fmaf(nH6, a2[j], mb2[j]);
                if (step == RELAX - 1) m0x[j] = mb0[j];
                if (probe) part += (mb0[j] - m0x[j]) * pmw[j];
            }
            SA[e]     = make_float4(mb0[0], mb1[0], mb2[0], 0.f);
            SA[e + 1] = make_float4(mb0[1], mb1[1], mb2[1], 0.f);
            if (ring) {
                __stcg((float2*)&m_out[0*NG + g], make_float2(mb0[0], mb0[1]));
                __stcg((float2*)&m_out[1*NG + g], make_float2(mb1[0], mb1[1]));
                __stcg((float2*)&m_out[2*NG + g], make_float2(mb2[0], mb2[1]));
            }
        }

        if (step == NSTEPS - 1) {
            if (probe && hasp) {
                #pragma unroll
                for (int o = 16; o; o >>= 1) part += __shfl_down_sync(0xffffffffu, part, o);
                if ((tid & 31) == 0) red[tid >> 5] = part;
                __syncthreads();
                if (tid < 32) {
                    float v2 = (tid < NT/32) ? red[tid] : 0.f;
                    #pragma unroll
                    for (int o = 8; o; o >>= 1) v2 += __shfl_down_sync(0xffffffffu, v2, o);
                    if (tid == 0) atomicAdd(&out[step - RELAX], v2 * s_pminv);
                }
            }
            break;
        }

        // ---- arrive: fire-and-forget, orders prior ring stores ----
        __syncthreads();
        if (tid == 0)
            asm volatile("red.add.release.gpu.u32 [%0], %1;"
                         :: "l"(&g_count), "r"(1u) : "memory");

        // ---- probe reduction overlaps other CTAs' spin ----
        if (probe && hasp) {
            #pragma unroll
            for (int o = 16; o; o >>= 1) part += __shfl_down_sync(0xffffffffu, part, o);
            if ((tid & 31) == 0) red[tid >> 5] = part;
            __syncthreads();
            if (tid < 32) {
                float v2 = (tid < NT/32) ? red[tid] : 0.f;
                #pragma unroll
                for (int o = 8; o; o >>= 1) v2 += __shfl_down_sync(0xffffffffu, v2, o);
                if (tid == 0) atomicAdd(&out[step - RELAX], v2 * s_pminv);
            }
        }

        // ---- wait: EVERY THREAD polls the monotonic counter directly ----
        // (removes the post-wait __syncthreads broadcast; each warp resumes
        //  on its own L2 observation; halo loads issue immediately after)
        {
            const unsigned need = (unsigned)(step + 1) * (unsigned)NCTA;
            unsigned v;
            do {
                asm volatile("ld.acquire.gpu.u32 %0, [%1];" : "=r"(v) : "l"(&g_count) : "memory");
            } while (v < need);
        }
    }
}

// ---------------- host launcher: ONE graph node ----------------
extern "C" void kernel_launch(void* const* d_in, const int* in_sizes, int n_in,
                              void* d_out, int out_size)
{
    const float* sig   = (const float*)d_in[0];
    const float* Bext  = (const float*)d_in[1];
    const float* Msat  = (const float*)d_in[2];
    const float* src   = (const float*)d_in[3];
    const float* pmask = (const float*)d_in[4];
    float* out = (float*)d_out;

    dim3 grid(NBX, NBY);
    k_sim<<<grid, NT>>>(sig, Bext, Msat, src, pmask, out);
}

// round 13
// speedup vs baseline: 1.7209x; 1.7209x over previous
#include <cuda_runtime.h>

// ---------------- problem constants ----------------
#define NXg 256
#define NYg 256
#define NG  (NXg*NYg)

// tile: interior 16(x) x 32(y), halo 4 -> ext 24x40; strips of 2 in y
#define IXt 16
#define IYt 32
#define Hh  4
#define EXt 24
#define EYt 40
#define EXT (EXt*EYt)      // 960
#define SW   2
#define NSTR (EYt/SW)      // 20
#define NSTRIPS (EXt*NSTR) // 480
#define NT   512
#define NBX (NYg/IYt)      // 8
#define NBY (NXg/IXt)      // 16
#define NCTA (NBX*NBY)     // 128 CTAs <= 148 SMs -> co-resident
#define RELAX  100
#define TSTEPS 1024
#define NSTEPS (RELAX + TSTEPS)

// ---------------- device state ----------------
__device__ float g_m[2][3*NG];   // ping-pong exchange state
__device__ unsigned g_count;     // MONOTONIC arrival counter (reset at kernel start)
__device__ unsigned g_ibar;      // init barrier counter (self-resetting)
__device__ unsigned g_isense;    // init barrier sense (2 flips/run -> replay-safe)

// init-only sense-reversing barrier (used exactly twice per run)
__device__ __forceinline__ void initbar(unsigned& lsense)
{
    __syncthreads();
    if (threadIdx.x == 0) {
        unsigned s = lsense ^ 1u;
        lsense = s;
        unsigned old;
        asm volatile("atom.add.acq_rel.gpu.u32 %0, [%1], 1;"
                     : "=r"(old) : "l"(&g_ibar) : "memory");
        if (old == NCTA - 1u) {
            asm volatile("st.relaxed.gpu.u32 [%0], %1;" :: "l"(&g_ibar), "r"(0u) : "memory");
            asm volatile("st.release.gpu.u32 [%0], %1;" :: "l"(&g_isense), "r"(s) : "memory");
        } else {
            unsigned v;
            do {
                asm volatile("ld.acquire.gpu.u32 %0, [%1];" : "=r"(v) : "l"(&g_isense) : "memory");
            } while (v != s);
        }
    }
    __syncthreads();
}

// max RK substage (1..4) at which a strip must still be computed; -1 = dead.
__device__ __forceinline__ int strip_cap(int ex, int sy, int gx0, int gy0)
{
    int gx = gx0 + ex;
    int cap = -1;
    #pragma unroll
    for (int j = 0; j < SW; j++) {
        int ey = SW*sy + j;
        int gy = gy0 + ey;
        if (gx < 0 || gx >= NXg || gy < 0 || gy >= NYg) continue;
        int c = 99;
        if (gx0 >= 0)         c = min(c, ex);
        if (gx0 + EXt <= NXg) c = min(c, EXt - 1 - ex);
        if (gy0 >= 0)         c = min(c, ey);
        if (gy0 + EYt <= NYg) c = min(c, EYt - 1 - ey);
        cap = max(cap, min(c, 4));
    }
    return cap;
}

__global__ void __launch_bounds__(NT, 1)
k_sim(const float* __restrict__ sig,  const float* __restrict__ Bext,
      const float* __restrict__ Msat, const float* __restrict__ src,
      const float* __restrict__ pmask, float* __restrict__ out)
{
    __shared__ __align__(16) float4 SA[EXT];   // (mx,my,mz,pad) per cell
    __shared__ __align__(16) float4 SB[EXT];
    __shared__ float red[NT/32];
    __shared__ float s_pminv;
    __shared__ float s_sig[TSTEPS];
    __shared__ signed char sClass[NSTRIPS];
    __shared__ short sOwner[NSTRIPS];

    const int tid = threadIdx.x;
    const int gx0 = (int)blockIdx.y * IXt - Hh;
    const int gy0 = (int)blockIdx.x * IYt - Hh;
    const bool cta0 = (blockIdx.x == 0 && blockIdx.y == 0);

    // ---- deterministic cap-ordered thread->strip mapping ----
    if (tid < NSTRIPS) {
        sClass[tid] = (signed char)strip_cap(tid / NSTR, tid % NSTR, gx0, gy0);
        sOwner[tid] = -1;
    }
    __syncthreads();
    if (tid < NSTRIPS && sClass[tid] >= 0) {
        int myc = sClass[tid];
        int r = 0;
        for (int s = 0; s < NSTRIPS; ++s) {
            int cs = sClass[s];
            r += (cs > myc) || (cs == myc && s < tid);
        }
        sOwner[r] = (short)tid;
    }
    __syncthreads();
    const int myStrip = (tid < NSTRIPS) ? (int)sOwner[tid] : -1;
    const bool live = (myStrip >= 0);
    const int ex  = live ? myStrip / NSTR : 0;
    const int sy  = live ? myStrip % NSTR : 0;
    const int scap = live ? strip_cap(ex, sy, gx0, gy0) : -1;

    const int gx  = gx0 + ex;
    const int gyb = gy0 + SW*sy;
    const int e   = ex*EYt + SW*sy;

    const int gxc = min(max(gx, 0), NXg - 1);
    const int gyc = min(max(gyb, 0), NYg - SW);
    const int g   = gxc*NYg + gyc;

    const int exm = (ex == 0       || gx <= 0)       ? ex : ex - 1;
    const int exq = (ex == EXt - 1 || gx >= NXg - 1) ? ex : ex + 1;
    const int emb = exm*EYt + SW*sy;
    const int epb = exq*EYt + SW*sy;
    const int yL = (sy == 0        || gyb <= 0)                ? e          : e - 1;
    const int yR = (sy == NSTR - 1 || gyb + SW - 1 >= NYg - 1) ? e + SW - 1 : e + SW;

    const bool sint = (scap >= 4);   // interior <=> needed through stage 4
    const bool ring = sint && (ex < Hh + 4 || ex >= Hh + IXt - 4 ||
                               sy < Hh/SW + 2 || sy >= (Hh + IYt)/SW - 2);

    const float MU0f    = (float)(4e-7 * 3.14159265358979323846);
    const float TWO_A   = (float)(2.0 * 3.65e-12);
    const float INV_DX2 = (float)(1.0 / (50e-9 * 50e-9));
    const double hd  = 1.7595e11 * 5e-12;
    const float c05  = (float)(0.5 * hd);
    const float cfl  = (float)hd;
    const float h6   = (float)(hd / 6.0);
    const float i_rx = (float)(1.0 / (1.0 + 0.5 * 0.5));
    const float i_rn = (float)(1.0 / (1.0 + 0.01 * 0.01));
    // folded (negative) coefficients: st = fma(nC, k', mb), k' = p + alpha*q
    const float nC05_rx = -(c05 * i_rx), nCfl_rx = -(cfl * i_rx), nH6_rx = -(h6 * i_rx);
    const float nC05_rn = -(c05 * i_rn), nCfl_rn = -(cfl * i_rn), nH6_rn = -(h6 * i_rn);

    // -------- static per-cell constants (registers, whole run) --------
    float rB0[SW], rB1[SW], rB2[SW], rS0[SW], rS1[SW], rS2[SW];
    float rCL[SW], rDg[SW], pmw[SW], m0x[SW];
    int anyp = 0;
    #pragma unroll
    for (int j = 0; j < SW; j++) {
        int gj = live ? gx*NYg + (gyb + j) : 0;   // live strips are fully in-domain
        float ms = Msat[gj];
        rCL[j] = (TWO_A / ms) * INV_DX2;
        rDg[j] = MU0f * ms;
        rB0[j] = Bext[0*NG + gj]; rB1[j] = Bext[1*NG + gj]; rB2[j] = Bext[2*NG + gj];
        rS0[j] = src [0*NG + gj]; rS1[j] = src [1*NG + gj]; rS2[j] = src [2*NG + gj];
        float pv = sint ? pmask[gj] : 0.f;
        pmw[j] = pv * ms;
        m0x[j] = 0.f;
        if (pv != 0.f) anyp = 1;
    }

    for (int i = tid; i < TSTEPS; i += NT) s_sig[i] = sig[i];
    if (cta0) {
        for (int i = tid; i < TSTEPS; i += NT) out[i] = 0.f;
        if (tid == 0)
            asm volatile("st.relaxed.gpu.u32 [%0], %1;" :: "l"(&g_count), "r"(0u) : "memory");
    }

    const int hasp = __syncthreads_or(anyp);
    if (hasp) {
        float s = 0.f;
        for (int i = tid; i < NG; i += NT) s += pmask[i];
        #pragma unroll
        for (int o = 16; o; o >>= 1) s += __shfl_down_sync(0xffffffffu, s, o);
        if ((tid & 31) == 0) red[tid >> 5] = s;
        __syncthreads();
        if (tid < 32) {
            float v = (tid < NT/32) ? red[tid] : 0.f;
            #pragma unroll
            for (int o = 8; o; o >>= 1) v += __shfl_down_sync(0xffffffffu, v, o);
            if (tid == 0) s_pminv = 1.f / v;
        }
    }

    unsigned lsense = 0;
    initbar(lsense);
    initbar(lsense);

    float mb0[SW], mb1[SW], mb2[SW];
    #pragma unroll
    for (int j = 0; j < SW; j++) { mb0[j] = 0.f; mb1[j] = 0.f; mb2[j] = 1.f; }
    if (live) {
        SA[e]     = make_float4(0.f, 0.f, 1.f, 0.f);
        SA[e + 1] = make_float4(0.f, 0.f, 1.f, 0.f);
    }
    __syncthreads();

    for (int step = 0; step < NSTEPS; ++step) {
        const bool  probe = (step >= RELAX);
        const float sv    = probe ? s_sig[step - RELAX] : 0.f;
        const float alpha = probe ? 0.01f : 0.5f;
        const float nC05  = probe ? nC05_rn : nC05_rx;
        const float nCfl  = probe ? nCfl_rn : nCfl_rx;
        const float nH6   = probe ? nH6_rn  : nH6_rx;
        const float* __restrict__ m_in  = g_m[(step + 1) & 1];
        float*       __restrict__ m_out = g_m[step & 1];

        // ---- halo refresh from L2 ----
        if (live && !sint && step > 0) {
            float2 a = __ldcg((const float2*)&m_in[0*NG + g]);
            float2 b = __ldcg((const float2*)&m_in[1*NG + g]);
            float2 c = __ldcg((const float2*)&m_in[2*NG + g]);
            mb0[0]=a.x; mb0[1]=a.y;
            mb1[0]=b.x; mb1[1]=b.y;
            mb2[0]=c.x; mb2[1]=c.y;
            SA[e]     = make_float4(a.x, b.x, c.x, 0.f);
            SA[e + 1] = make_float4(a.y, b.y, c.y, 0.f);
        }

        float tB0[SW], tB1[SW], tB2[SW];
        float st0[SW], st1[SW], st2[SW];
        float a0[SW], a1[SW], a2[SW];
        #pragma unroll
        for (int j = 0; j < SW; j++) {
            tB0[j] = fmaf(sv, rS0[j], rB0[j]);
            tB1[j] = fmaf(sv, rS1[j], rB1[j]);
            tB2[j] = fmaf(sv, rS2[j], rB2[j]);
            st0[j] = mb0[j]; st1[j] = mb1[j]; st2[j] = mb2[j];
            a0[j] = 0.f; a1[j] = 0.f; a2[j] = 0.f;
        }
        __syncthreads();

        // one RK substage; k' = p + alpha*q (sign & inv1a folded into coefs)
        auto stage = [&](const float4* __restrict__ S,
                         float4* __restrict__ D,
                         float nCoef, float w, bool writeD) {
            float4 xmA = S[emb],  xmB = S[emb + 1];   // x- neighbors (j=0,1)
            float4 xpA = S[epb],  xpB = S[epb + 1];   // x+ neighbors
            float4 ylv = S[yL];                        // y- neighbor of j=0
            float4 yrv = S[yR];                        // y+ neighbor of j=1
            float xm0[SW] = {xmA.x, xmB.x}, xm1[SW] = {xmA.y, xmB.y}, xm2[SW] = {xmA.z, xmB.z};
            float xp0[SW] = {xpA.x, xpB.x}, xp1[SW] = {xpA.y, xpB.y}, xp2[SW] = {xpA.z, xpB.z};
            #pragma unroll
            for (int j = 0; j < SW; j++) {
                float mx = st0[j], my = st1[j], mz = st2[j];
                float yl0 = j ? st0[j-1] : ylv.x;
                float yl1 = j ? st1[j-1] : ylv.y;
                float yl2 = j ? st2[j-1] : ylv.z;
                float yr0 = (j < SW-1) ? st0[j+1] : yrv.x;
                float yr1 = (j < SW-1) ? st1[j+1] : yrv.y;
                float yr2 = (j < SW-1) ? st2[j+1] : yrv.z;
                float l0 = xm0[j] + xp0[j] + yl0 + yr0 - 4.f*mx;
                float l1 = xm1[j] + xp1[j] + yl1 + yr1 - 4.f*my;
                float l2 = xm2[j] + xp2[j] + yl2 + yr2 - 4.f*mz;
                float Bx = fmaf(rCL[j], l0, tB0[j]);
                float By = fmaf(rCL[j], l1, tB1[j]);
                float Bz = fmaf(rCL[j], l2, tB2[j]) - rDg[j]*mz;
                float px = my*Bz - mz*By;
                float py = mz*Bx - mx*Bz;
                float pz = mx*By - my*Bx;
                float qx = my*pz - mz*py;
                float qy = mz*px - mx*pz;
                float qz = mx*py - my*px;
                float k0 = fmaf(alpha, qx, px);
                float k1 = fmaf(alpha, qy, py);
                float k2 = fmaf(alpha, qz, pz);
                a0[j] = fmaf(w, k0, a0[j]);
                a1[j] = fmaf(w, k1, a1[j]);
                a2[j] = fmaf(w, k2, a2[j]);
                st0[j] = fmaf(nCoef, k0, mb0[j]);
                st1[j] = fmaf(nCoef, k1, mb1[j]);
                st2[j] = fmaf(nCoef, k2, mb2[j]);
            }
            if (writeD) {
                D[e]     = make_float4(st0[0], st1[0], st2[0], 0.f);
                D[e + 1] = make_float4(st0[1], st1[1], st2[1], 0.f);
            }
        };

        if (scap >= 1) stage(SA, SB, nC05, 1.f, true);
        __syncthreads();
        if (scap >= 2) stage(SB, SA, nC05, 2.f, true);
        __syncthreads();
        if (scap >= 3) stage(SA, SB, nCfl, 2.f, true);
        __syncthreads();
        if (scap >= 4) stage(SB, SA, 0.f, 1.f, false);   // k4 folded into acc

        // ---- final m (interior): SA publish + exchange ring to L2 ----
        float part = 0.f;
        if (sint) {
            #pragma unroll
            for (int j = 0; j < SW; j++) {
                mb0[j] = fmaf(nH6, a0[j], mb0[j]);
                mb1[j] = fmaf(nH6, a1[j], mb1[j]);
                mb2[j] = fmaf(nH6, a2[j], mb2[j]);
                if (step == RELAX - 1) m0x[j] = mb0[j];
                if (probe) part += (mb0[j] - m0x[j]) * pmw[j];
            }
            SA[e]     = make_float4(mb0[0], mb1[0], mb2[0], 0.f);
            SA[e + 1] = make_float4(mb0[1], mb1[1], mb2[1], 0.f);
            if (ring) {
                __stcg((float2*)&m_out[0*NG + g], make_float2(mb0[0], mb0[1]));
                __stcg((float2*)&m_out[1*NG + g], make_float2(mb1[0], mb1[1]));
                __stcg((float2*)&m_out[2*NG + g], make_float2(mb2[0], mb2[1]));
            }
        }

        if (step == NSTEPS - 1) {
            if (probe && hasp) {
                #pragma unroll
                for (int o = 16; o; o >>= 1) part += __shfl_down_sync(0xffffffffu, part, o);
                if ((tid & 31) == 0) red[tid >> 5] = part;
                __syncthreads();
                if (tid < 32) {
                    float v2 = (tid < NT/32) ? red[tid] : 0.f;
                    #pragma unroll
                    for (int o = 8; o; o >>= 1) v2 += __shfl_down_sync(0xffffffffu, v2, o);
                    if (tid == 0) atomicAdd(&out[step - RELAX], v2 * s_pminv);
                }
            }
            break;
        }

        // ---- arrive: fire-and-forget, orders prior ring stores ----
        __syncthreads();
        if (tid == 0)
            asm volatile("red.add.release.gpu.u32 [%0], %1;"
                         :: "l"(&g_count), "r"(1u) : "memory");

        // ---- probe reduction overlaps other CTAs' spin ----
        if (probe && hasp) {
            #pragma unroll
            for (int o = 16; o; o >>= 1) part += __shfl_down_sync(0xffffffffu, part, o);
            if ((tid & 31) == 0) red[tid >> 5] = part;
            __syncthreads();
            if (tid < 32) {
                float v2 = (tid < NT/32) ? red[tid] : 0.f;
                #pragma unroll
                for (int o = 8; o; o >>= 1) v2 += __shfl_down_sync(0xffffffffu, v2, o);
                if (tid == 0) atomicAdd(&out[step - RELAX], v2 * s_pminv);
            }
        }

        // ---- wait: ONLY tid0 polls (128 pollers grid-wide), then broadcast ----
        if (tid == 0) {
            const unsigned need = (unsigned)(step + 1) * (unsigned)NCTA;
            unsigned v;
            do {
                asm volatile("ld.acquire.gpu.u32 %0, [%1];" : "=r"(v) : "l"(&g_count) : "memory");
            } while (v < need);
        }
        __syncthreads();
    }
}

// ---------------- host launcher: ONE graph node ----------------
extern "C" void kernel_launch(void* const* d_in, const int* in_sizes, int n_in,
                              void* d_out, int out_size)
{
    const float* sig   = (const float*)d_in[0];
    const float* Bext  = (const float*)d_in[1];
    const float* Msat  = (const float*)d_in[2];
    const float* src   = (const float*)d_in[3];
    const float* pmask = (const float*)d_in[4];
    float* out = (float*)d_out;

    dim3 grid(NBX, NBY);
    k_sim<<<grid, NT>>>(sig, Bext, Msat, src, pmask, out);
}

// round 14
// speedup vs baseline: 2.0066x; 1.1661x over previous
#include <cuda_runtime.h>

// ---------------- problem constants ----------------
#define NXg 256
#define NYg 256
#define NG  (NXg*NYg)

// tile: interior 16(x) x 32(y), halo 4 -> ext 24x40; strips of 2 in y
#define IXt 16
#define IYt 32
#define Hh  4
#define EXt 24
#define EYt 40
#define EXT (EXt*EYt)      // 960
#define SW   2
#define NSTR (EYt/SW)      // 20
#define NSTRIPS (EXt*NSTR) // 480
#define NT   512
#define NBX (NYg/IYt)      // 8
#define NBY (NXg/IXt)      // 16
#define NCTA (NBX*NBY)     // 128 CTAs <= 148 SMs -> co-resident
#define RELAX  100
#define TSTEPS 1024
#define NSTEPS (RELAX + TSTEPS)

// ---------------- device state ----------------
__device__ float g_m[2][3*NG];   // ping-pong exchange state
__device__ unsigned g_count;     // MONOTONIC arrival counter (reset at kernel start)
__device__ unsigned g_ibar;      // init barrier counter (self-resetting)
__device__ unsigned g_isense;    // init barrier sense (2 flips/run -> replay-safe)

__device__ __forceinline__ void initbar(unsigned& lsense)
{
    __syncthreads();
    if (threadIdx.x == 0) {
        unsigned s = lsense ^ 1u;
        lsense = s;
        unsigned old;
        asm volatile("atom.add.acq_rel.gpu.u32 %0, [%1], 1;"
                     : "=r"(old) : "l"(&g_ibar) : "memory");
        if (old == NCTA - 1u) {
            asm volatile("st.relaxed.gpu.u32 [%0], %1;" :: "l"(&g_ibar), "r"(0u) : "memory");
            asm volatile("st.release.gpu.u32 [%0], %1;" :: "l"(&g_isense), "r"(s) : "memory");
        } else {
            unsigned v;
            do {
                asm volatile("ld.acquire.gpu.u32 %0, [%1];" : "=r"(v) : "l"(&g_isense) : "memory");
            } while (v != s);
        }
    }
    __syncthreads();
}

// class: 0 = dead, 1..4 = cap0..cap3 (halo rings), 5 = edge-interior, 6 = deep-interior.
// cap rule per cell identical to validated R2/R10 smax.
__device__ __forceinline__ int strip_class(int ex, int sy, int gx0, int gy0)
{
    int gx = gx0 + ex;
    int cap = -1;
    #pragma unroll
    for (int j = 0; j < SW; j++) {
        int ey = SW*sy + j;
        int gy = gy0 + ey;
        if (gx < 0 || gx >= NXg || gy < 0 || gy >= NYg) continue;
        int c = 99;
        if (gx0 >= 0)         c = min(c, ex);
        if (gx0 + EXt <= NXg) c = min(c, EXt - 1 - ex);
        if (gy0 >= 0)         c = min(c, ey);
        if (gy0 + EYt <= NYg) c = min(c, EYt - 1 - ey);
        cap = max(cap, min(c, 4));
    }
    if (cap < 0) return 0;
    if (cap < 4) return cap + 1;
    // deep test: all stage-1 stencil cells are interior (never halo-refreshed)
    int gyb = gy0 + SW*sy;
    int exm = (ex == 0       || gx <= 0)       ? ex : ex - 1;
    int exq = (ex == EXt - 1 || gx >= NXg - 1) ? ex : ex + 1;
    int ceyL = (sy == 0        || gyb <= 0)                ? SW*sy          : SW*sy - 1;
    int ceyR = (sy == NSTR - 1 || gyb + SW - 1 >= NYg - 1) ? SW*sy + SW - 1 : SW*sy + SW;
    bool deep = (exm >= Hh) && (exq < Hh + IXt) && (ceyL >= Hh) && (ceyR < Hh + IYt);
    return deep ? 6 : 5;
}

__global__ void __launch_bounds__(NT, 1)
k_sim(const float* __restrict__ sig,  const float* __restrict__ Bext,
      const float* __restrict__ Msat, const float* __restrict__ src,
      const float* __restrict__ pmask, float* __restrict__ out)
{
    __shared__ __align__(16) float SA[3][EXT];
    __shared__ __align__(16) float SB[3][EXT];
    __shared__ float red[NT/32];
    __shared__ float s_pminv;
    __shared__ float s_sig[TSTEPS];
    __shared__ signed char sClass[NSTRIPS];
    __shared__ short sOwner[NSTRIPS];

    const int tid = threadIdx.x;
    const int gx0 = (int)blockIdx.y * IXt - Hh;
    const int gy0 = (int)blockIdx.x * IYt - Hh;
    const bool cta0 = (blockIdx.x == 0 && blockIdx.y == 0);

    // ---- deterministic class-ASCENDING thread->strip mapping ----
    // live strips ranked ascending by class: tid0 = cap0 (no pre-wait work),
    // deep-interior strips land in the top live warps; dead threads at the end.
    if (tid < NSTRIPS) {
        sClass[tid] = (signed char)strip_class(tid / NSTR, tid % NSTR, gx0, gy0);
        sOwner[tid] = -1;
    }
    __syncthreads();
    if (tid < NSTRIPS && sClass[tid] > 0) {
        int myc = sClass[tid];
        int r = 0;
        for (int s = 0; s < NSTRIPS; ++s) {
            int cs = sClass[s];
            r += (cs > 0) && ((cs < myc) || (cs == myc && s < tid));
        }
        sOwner[r] = (short)tid;
    }
    __syncthreads();
    const int myStrip = (tid < NSTRIPS) ? (int)sOwner[tid] : -1;
    const bool live = (myStrip >= 0);
    const int cls  = live ? (int)sClass[myStrip] : 0;
    const int ex   = live ? myStrip / NSTR : 0;
    const int sy   = live ? myStrip % NSTR : 0;
    const int scap = (cls == 0) ? -1 : ((cls >= 5) ? 4 : cls - 1);
    const bool deep = (cls == 6);

    const int gx  = gx0 + ex;
    const int gyb = gy0 + SW*sy;
    const int e   = ex*EYt + SW*sy;

    const int gxc = min(max(gx, 0), NXg - 1);
    const int gyc = min(max(gyb, 0), NYg - SW);
    const int g   = gxc*NYg + gyc;

    const int exm = (ex == 0       || gx <= 0)       ? ex : ex - 1;
    const int exq = (ex == EXt - 1 || gx >= NXg - 1) ? ex : ex + 1;
    const int emb = exm*EYt + SW*sy;
    const int epb = exq*EYt + SW*sy;
    const int yL = (sy == 0        || gyb <= 0)                ? e          : e - 1;
    const int yR = (sy == NSTR - 1 || gyb + SW - 1 >= NYg - 1) ? e + SW - 1 : e + SW;

    const bool sint = (scap >= 4);
    const bool ring = sint && (ex < Hh + 4 || ex >= Hh + IXt - 4 ||
                               sy < Hh/SW + 2 || sy >= (Hh + IYt)/SW - 2);

    const float MU0f    = (float)(4e-7 * 3.14159265358979323846);
    const float TWO_A   = (float)(2.0 * 3.65e-12);
    const float INV_DX2 = (float)(1.0 / (50e-9 * 50e-9));
    const double hd  = 1.7595e11 * 5e-12;
    const float c05  = (float)(0.5 * hd);
    const float cfl  = (float)hd;
    const float h6   = (float)(hd / 6.0);
    const float i_rx = (float)(1.0 / (1.0 + 0.5 * 0.5));
    const float i_rn = (float)(1.0 / (1.0 + 0.01 * 0.01));
    const float nC05_rx = -(c05 * i_rx), nCfl_rx = -(cfl * i_rx), nH6_rx = -(h6 * i_rx);
    const float nC05_rn = -(c05 * i_rn), nCfl_rn = -(cfl * i_rn), nH6_rn = -(h6 * i_rn);

    // -------- static per-cell constants (registers, whole run) --------
    float rB0[SW], rB1[SW], rB2[SW], rS0[SW], rS1[SW], rS2[SW];
    float rCL[SW], rDg[SW], pmw[SW], m0x[SW];
    int anyp = 0;
    #pragma unroll
    for (int j = 0; j < SW; j++) {
        int gj = live ? gx*NYg + (gyb + j) : 0;
        float ms = Msat[gj];
        rCL[j] = (TWO_A / ms) * INV_DX2;
        rDg[j] = MU0f * ms;
        rB0[j] = Bext[0*NG + gj]; rB1[j] = Bext[1*NG + gj]; rB2[j] = Bext[2*NG + gj];
        rS0[j] = src [0*NG + gj]; rS1[j] = src [1*NG + gj]; rS2[j] = src [2*NG + gj];
        float pv = sint ? pmask[gj] : 0.f;
        pmw[j] = pv * ms;
        m0x[j] = 0.f;
        if (pv != 0.f) anyp = 1;
    }

    for (int i = tid; i < TSTEPS; i += NT) s_sig[i] = sig[i];
    if (cta0) {
        for (int i = tid; i < TSTEPS; i += NT) out[i] = 0.f;
        if (tid == 0)
            asm volatile("st.relaxed.gpu.u32 [%0], %1;" :: "l"(&g_count), "r"(0u) : "memory");
    }

    const int hasp = __syncthreads_or(anyp);
    if (hasp) {
        float s = 0.f;
        for (int i = tid; i < NG; i += NT) s += pmask[i];
        #pragma unroll
        for (int o = 16; o; o >>= 1) s += __shfl_down_sync(0xffffffffu, s, o);
        if ((tid & 31) == 0) red[tid >> 5] = s;
        __syncthreads();
        if (tid < 32) {
            float v = (tid < NT/32) ? red[tid] : 0.f;
            #pragma unroll
            for (int o = 8; o; o >>= 1) v += __shfl_down_sync(0xffffffffu, v, o);
            if (tid == 0) s_pminv = 1.f / v;
        }
    }

    unsigned lsense = 0;
    initbar(lsense);
    initbar(lsense);

    // persistent per-thread step state (survives across the barrier)
    float mb0[SW], mb1[SW], mb2[SW];
    float tB0[SW], tB1[SW], tB2[SW];
    float st0[SW], st1[SW], st2[SW];
    float a0[SW], a1[SW], a2[SW];
    #pragma unroll
    for (int j = 0; j < SW; j++) { mb0[j] = 0.f; mb1[j] = 0.f; mb2[j] = 1.f; }
    if (live) {
        *(float2*)&SA[0][e] = make_float2(0.f, 0.f);
        *(float2*)&SA[1][e] = make_float2(0.f, 0.f);
        *(float2*)&SA[2][e] = make_float2(1.f, 1.f);
    }
    __syncthreads();

    // one RK substage; k' = p + alpha*q (sign & inv1a folded into coefs)
    auto stage = [&](const float (*__restrict__ S)[EXT],
                     float (*__restrict__ D)[EXT],
                     float alph, float nCoef, float w, bool writeD) {
        float2 nm0 = *(const float2*)&S[0][emb];
        float2 nm1 = *(const float2*)&S[1][emb];
        float2 nm2 = *(const float2*)&S[2][emb];
        float2 np0 = *(const float2*)&S[0][epb];
        float2 np1 = *(const float2*)&S[1][epb];
        float2 np2 = *(const float2*)&S[2][epb];
        float lf0 = S[0][yL], lf1 = S[1][yL], lf2 = S[2][yL];
        float rg0 = S[0][yR], rg1 = S[1][yR], rg2 = S[2][yR];
        float xm0[SW] = {nm0.x, nm0.y}, xm1[SW] = {nm1.x, nm1.y}, xm2[SW] = {nm2.x, nm2.y};
        float xp0[SW] = {np0.x, np0.y}, xp1[SW] = {np1.x, np1.y}, xp2[SW] = {np2.x, np2.y};
        #pragma unroll
        for (int j = 0; j < SW; j++) {
            float mx = st0[j], my = st1[j], mz = st2[j];
            float yl0 = j ? st0[j-1] : lf0;
            float yl1 = j ? st1[j-1] : lf1;
            float yl2 = j ? st2[j-1] : lf2;
            float yr0 = (j < SW-1) ? st0[j+1] : rg0;
            float yr1 = (j < SW-1) ? st1[j+1] : rg1;
            float yr2 = (j < SW-1) ? st2[j+1] : rg2;
            float l0 = xm0[j] + xp0[j] + yl0 + yr0 - 4.f*mx;
            float l1 = xm1[j] + xp1[j] + yl1 + yr1 - 4.f*my;
            float l2 = xm2[j] + xp2[j] + yl2 + yr2 - 4.f*mz;
            float Bx = fmaf(rCL[j], l0, tB0[j]);
            float By = fmaf(rCL[j], l1, tB1[j]);
            float Bz = fmaf(rCL[j], l2, tB2[j]) - rDg[j]*mz;
            float px = my*Bz - mz*By;
            float py = mz*Bx - mx*Bz;
            float pz = mx*By - my*Bx;
            float qx = my*pz - mz*py;
            float qy = mz*px - mx*pz;
            float qz = mx*py - my*px;
            float k0 = fmaf(alph, qx, px);
            float k1 = fmaf(alph, qy, py);
            float k2 = fmaf(alph, qz, pz);
            a0[j] = fmaf(w, k0, a0[j]);
            a1[j] = fmaf(w, k1, a1[j]);
            a2[j] = fmaf(w, k2, a2[j]);
            st0[j] = fmaf(nCoef, k0, mb0[j]);
            st1[j] = fmaf(nCoef, k1, mb1[j]);
            st2[j] = fmaf(nCoef, k2, mb2[j]);
        }
        if (writeD) {
            *(float2*)&D[0][e] = make_float2(st0[0], st0[1]);
            *(float2*)&D[1][e] = make_float2(st1[0], st1[1]);
            *(float2*)&D[2][e] = make_float2(st2[0], st2[1]);
        }
    };

    // step-0 setup (sv = 0, relax)
    #pragma unroll
    for (int j = 0; j < SW; j++) {
        tB0[j] = rB0[j]; tB1[j] = rB1[j]; tB2[j] = rB2[j];
        st0[j] = mb0[j]; st1[j] = mb1[j]; st2[j] = mb2[j];
        a0[j] = 0.f; a1[j] = 0.f; a2[j] = 0.f;
    }

    for (int step = 0; step < NSTEPS; ++step) {
        const bool  probe = (step >= RELAX);
        const float alpha = probe ? 0.01f : 0.5f;
        const float nC05  = probe ? nC05_rn : nC05_rx;
        const float nCfl  = probe ? nCfl_rn : nCfl_rx;
        const float nH6   = probe ? nH6_rn  : nH6_rx;
        const float* __restrict__ m_in  = g_m[(step + 1) & 1];
        float*       __restrict__ m_out = g_m[step & 1];

        // ---- halo refresh from L2 (setup for this step done in prev tail) ----
        if (live && !sint && step > 0) {
            float2 a = __ldcg((const float2*)&m_in[0*NG + g]);
            float2 b = __ldcg((const float2*)&m_in[1*NG + g]);
            float2 c = __ldcg((const float2*)&m_in[2*NG + g]);
            mb0[0]=a.x; mb0[1]=a.y;
            mb1[0]=b.x; mb1[1]=b.y;
            mb2[0]=c.x; mb2[1]=c.y;
            st0[0]=a.x; st0[1]=a.y;
            st1[0]=b.x; st1[1]=b.y;
            st2[0]=c.x; st2[1]=c.y;
            *(float2*)&SA[0][e] = a; *(float2*)&SA[1][e] = b; *(float2*)&SA[2][e] = c;
        }
        __syncthreads();   // halo SA writes visible before stage-1 reads

        // stage 1 (deep strips already did it in the previous tail)
        if (scap >= 1 && (!deep || step == 0))
            stage(SA, SB, alpha, nC05, 1.f, true);
        __syncthreads();
        if (scap >= 2) stage(SB, SA, alpha, nC05, 2.f, true);
        __syncthreads();
        if (scap >= 3) stage(SA, SB, alpha, nCfl, 2.f, true);
        __syncthreads();
        if (scap >= 4) stage(SB, SA, alpha, 0.f, 1.f, false);   // k4 folded into acc

        // ---- final m (interior): SA publish + exchange ring to L2 ----
        float part = 0.f;
        if (sint) {
            #pragma unroll
            for (int j = 0; j < SW; j++) {
                mb0[j] = fmaf(nH6, a0[j], mb0[j]);
                mb1[j] = fmaf(nH6, a1[j], mb1[j]);
                mb2[j] = fmaf(nH6, a2[j], mb2[j]);
                if (step == RELAX - 1) m0x[j] = mb0[j];
                if (probe) part += (mb0[j] - m0x[j]) * pmw[j];
            }
            float2 a = make_float2(mb0[0], mb0[1]);
            float2 b = make_float2(mb1[0], mb1[1]);
            float2 c = make_float2(mb2[0], mb2[1]);
            *(float2*)&SA[0][e] = a; *(float2*)&SA[1][e] = b; *(float2*)&SA[2][e] = c;
            if (ring) {
                __stcg((float2*)&m_out[0*NG + g], a);
                __stcg((float2*)&m_out[1*NG + g], b);
                __stcg((float2*)&m_out[2*NG + g], c);
            }
        }

        if (step == NSTEPS - 1) {
            if (probe && hasp) {
                #pragma unroll
                for (int o = 16; o; o >>= 1) part += __shfl_down_sync(0xffffffffu, part, o);
                if ((tid & 31) == 0) red[tid >> 5] = part;
                __syncthreads();
                if (tid < 32) {
                    float v2 = (tid < NT/32) ? red[tid] : 0.f;
                    #pragma unroll
                    for (int o = 8; o; o >>= 1) v2 += __shfl_down_sync(0xffffffffu, v2, o);
                    if (tid == 0) atomicAdd(&out[step - RELAX], v2 * s_pminv);
                }
            }
            break;
        }

        // ---- arrive: fire-and-forget, orders prior ring stores ----
        __syncthreads();
        if (tid == 0)
            asm volatile("red.add.release.gpu.u32 [%0], %1;"
                         :: "l"(&g_count), "r"(1u) : "memory");

        // ---- probe reduction overlaps other CTAs' spin (2 CTAs only) ----
        if (probe && hasp) {
            #pragma unroll
            for (int o = 16; o; o >>= 1) part += __shfl_down_sync(0xffffffffu, part, o);
            if ((tid & 31) == 0) red[tid >> 5] = part;
            __syncthreads();
            if (tid < 32) {
                float v2 = (tid < NT/32) ? red[tid] : 0.f;
                #pragma unroll
                for (int o = 8; o; o >>= 1) v2 += __shfl_down_sync(0xffffffffu, v2, o);
                if (tid == 0) atomicAdd(&out[step - RELAX], v2 * s_pminv);
            }
        }

        // ---- early next-step setup + deep stage-1, hidden in the wait window ----
        {
            const int  stepn = step + 1;
            const bool prbn  = (stepn >= RELAX);
            const float svn  = prbn ? s_sig[stepn - RELAX] : 0.f;
            const float aln  = prbn ? 0.01f : 0.5f;
            const float nC5n = prbn ? nC05_rn : nC05_rx;
            #pragma unroll
            for (int j = 0; j < SW; j++) {
                tB0[j] = fmaf(svn, rS0[j], rB0[j]);
                tB1[j] = fmaf(svn, rS1[j], rB1[j]);
                tB2[j] = fmaf(svn, rS2[j], rB2[j]);
                st0[j] = mb0[j]; st1[j] = mb1[j]; st2[j] = mb2[j];
                a0[j] = 0.f; a1[j] = 0.f; a2[j] = 0.f;
            }
            // deep stage-1 of the NEXT step: reads own-CTA interior SA only
            // (final-written above, ordered by the pre-arrive sync); writes SB.
            if (deep) stage(SA, SB, aln, nC5n, 1.f, true);
        }

        // ---- wait: tid0 (cap0 strip: no pre-wait compute) polls; broadcast ----
        if (tid == 0) {
            const unsigned need = (unsigned)(step + 1) * (unsigned)NCTA;
            unsigned v;
            do {
                asm volatile("ld.acquire.gpu.u32 %0, [%1];" : "=r"(v) : "l"(&g_count) : "memory");
            } while (v < need);
        }
        __syncthreads();
    }
}

// ---------------- host launcher: ONE graph node ----------------
extern "C" void kernel_launch(void* const* d_in, const int* in_sizes, int n_in,
                              void* d_out, int out_size)
{
    const float* sig   = (const float*)d_in[0];
    const float* Bext  = (const float*)d_in[1];
    const float* Msat  = (const float*)d_in[2];
    const float* src   = (const float*)d_in[3];
    const float* pmask = (const float*)d_in[4];
    float* out = (float*)d_out;

    dim3 grid(NBX, NBY);
    k_sim<<<grid, NT>>>(sig, Bext, Msat, src, pmask, out);
}

// round 15
// speedup vs baseline: 2.0383x; 1.0158x over previous
#include <cuda_runtime.h>

// ---------------- problem constants ----------------
#define NXg 256
#define NYg 256
#define NG  (NXg*NYg)

// tile: interior 16(x) x 32(y), halo 4 -> ext 24x40; strips of 2 in y
#define IXt 16
#define IYt 32
#define Hh  4
#define EXt 24
#define EYt 40
#define EXT (EXt*EYt)      // 960
#define SW   2
#define NSTR (EYt/SW)      // 20
#define NSTRIPS (EXt*NSTR) // 480
#define NT   512
#define NBX (NYg/IYt)      // 8
#define NBY (NXg/IXt)      // 16
#define NCTA (NBX*NBY)     // 128 CTAs <= 148 SMs -> co-resident
#define RELAX  100
#define TSTEPS 1024
#define NSTEPS (RELAX + TSTEPS)

typedef unsigned long long u64;

// ---------------- packed f32x2 helpers ----------------
__device__ __forceinline__ u64 f2pk(float lo, float hi){
    u64 r; unsigned a = __float_as_uint(lo), b = __float_as_uint(hi);
    asm("mov.b64 %0,{%1,%2};" : "=l"(r) : "r"(a), "r"(b)); return r;
}
__device__ __forceinline__ void f2up(u64 v, float& lo, float& hi){
    unsigned a, b; asm("mov.b64 {%0,%1},%2;" : "=r"(a), "=r"(b) : "l"(v));
    lo = __uint_as_float(a); hi = __uint_as_float(b);
}
__device__ __forceinline__ u64 f2add(u64 a, u64 b){
    u64 d; asm("add.rn.f32x2 %0,%1,%2;" : "=l"(d) : "l"(a), "l"(b)); return d;
}
__device__ __forceinline__ u64 f2mul(u64 a, u64 b){
    u64 d; asm("mul.rn.f32x2 %0,%1,%2;" : "=l"(d) : "l"(a), "l"(b)); return d;
}
__device__ __forceinline__ u64 f2fma(u64 a, u64 b, u64 c){
    u64 d; asm("fma.rn.f32x2 %0,%1,%2,%3;" : "=l"(d) : "l"(a), "l"(b), "l"(c)); return d;
}
__device__ __forceinline__ u64 f2neg(u64 a){ return a ^ 0x8000000080000000ULL; }

// ---------------- device state ----------------
__device__ float g_m[2][3*NG];   // ping-pong exchange state
__device__ unsigned g_count;     // MONOTONIC arrival counter (reset at kernel start)
__device__ unsigned g_ibar;      // init barrier counter (self-resetting)
__device__ unsigned g_isense;    // init barrier sense (2 flips/run -> replay-safe)

// init-only sense-reversing barrier (used exactly twice per run)
__device__ __forceinline__ void initbar(unsigned& lsense)
{
    __syncthreads();
    if (threadIdx.x == 0) {
        unsigned s = lsense ^ 1u;
        lsense = s;
        unsigned old;
        asm volatile("atom.add.acq_rel.gpu.u32 %0, [%1], 1;"
                     : "=r"(old) : "l"(&g_ibar) : "memory");
        if (old == NCTA - 1u) {
            asm volatile("st.relaxed.gpu.u32 [%0], %1;" :: "l"(&g_ibar), "r"(0u) : "memory");
            asm volatile("st.release.gpu.u32 [%0], %1;" :: "l"(&g_isense), "r"(s) : "memory");
        } else {
            unsigned v;
            do {
                asm volatile("ld.acquire.gpu.u32 %0, [%1];" : "=r"(v) : "l"(&g_isense) : "memory");
            } while (v != s);
        }
    }
    __syncthreads();
}

// max RK substage (1..4) at which a strip must still be computed; -1 = dead.
__device__ __forceinline__ int strip_cap(int ex, int sy, int gx0, int gy0)
{
    int gx = gx0 + ex;
    int cap = -1;
    #pragma unroll
    for (int j = 0; j < SW; j++) {
        int ey = SW*sy + j;
        int gy = gy0 + ey;
        if (gx < 0 || gx >= NXg || gy < 0 || gy >= NYg) continue;
        int c = 99;
        if (gx0 >= 0)         c = min(c, ex);
        if (gx0 + EXt <= NXg) c = min(c, EXt - 1 - ex);
        if (gy0 >= 0)         c = min(c, ey);
        if (gy0 + EYt <= NYg) c = min(c, EYt - 1 - ey);
        cap = max(cap, min(c, 4));
    }
    return cap;
}

__global__ void __launch_bounds__(NT, 1)
k_sim(const float* __restrict__ sig,  const float* __restrict__ Bext,
      const float* __restrict__ Msat, const float* __restrict__ src,
      const float* __restrict__ pmask, float* __restrict__ out)
{
    __shared__ __align__(16) float SA[3][EXT];
    __shared__ __align__(16) float SB[3][EXT];
    __shared__ float red[NT/32];
    __shared__ float s_pminv;
    __shared__ float s_sig[TSTEPS];
    __shared__ signed char sClass[NSTRIPS];
    __shared__ short sOwner[NSTRIPS];

    const int tid = threadIdx.x;
    const int gx0 = (int)blockIdx.y * IXt - Hh;
    const int gy0 = (int)blockIdx.x * IYt - Hh;
    const bool cta0 = (blockIdx.x == 0 && blockIdx.y == 0);

    // ---- deterministic cap-ordered (descending) thread->strip mapping ----
    if (tid < NSTRIPS) {
        sClass[tid] = (signed char)strip_cap(tid / NSTR, tid % NSTR, gx0, gy0);
        sOwner[tid] = -1;
    }
    __syncthreads();
    if (tid < NSTRIPS && sClass[tid] >= 0) {
        int myc = sClass[tid];
        int r = 0;
        for (int s = 0; s < NSTRIPS; ++s) {
            int cs = sClass[s];
            r += (cs > myc) || (cs == myc && s < tid);
        }
        sOwner[r] = (short)tid;
    }
    __syncthreads();
    const int myStrip = (tid < NSTRIPS) ? (int)sOwner[tid] : -1;
    const bool live = (myStrip >= 0);
    const int ex  = live ? myStrip / NSTR : 0;
    const int sy  = live ? myStrip % NSTR : 0;
    const int scap = live ? strip_cap(ex, sy, gx0, gy0) : -1;

    const int gx  = gx0 + ex;
    const int gyb = gy0 + SW*sy;
    const int e   = ex*EYt + SW*sy;   // even -> 8B-aligned u64 smem slot

    const int gxc = min(max(gx, 0), NXg - 1);
    const int gyc = min(max(gyb, 0), NYg - SW);
    const int g   = gxc*NYg + gyc;

    const int exm = (ex == 0       || gx <= 0)       ? ex : ex - 1;
    const int exq = (ex == EXt - 1 || gx >= NXg - 1) ? ex : ex + 1;
    const int emb = exm*EYt + SW*sy;
    const int epb = exq*EYt + SW*sy;
    const int yL = (sy == 0        || gyb <= 0)                ? e          : e - 1;
    const int yR = (sy == NSTR - 1 || gyb + SW - 1 >= NYg - 1) ? e + SW - 1 : e + SW;

    const bool sint = (scap >= 4);
    const bool ring = sint && (ex < Hh + 4 || ex >= Hh + IXt - 4 ||
                               sy < Hh/SW + 2 || sy >= (Hh + IYt)/SW - 2);

    const float MU0f    = (float)(4e-7 * 3.14159265358979323846);
    const float TWO_A   = (float)(2.0 * 3.65e-12);
    const float INV_DX2 = (float)(1.0 / (50e-9 * 50e-9));
    const double hd  = 1.7595e11 * 5e-12;
    const float c05  = (float)(0.5 * hd);
    const float cfl  = (float)hd;
    const float h6   = (float)(hd / 6.0);
    const float i_rx = (float)(1.0 / (1.0 + 0.5 * 0.5));
    const float i_rn = (float)(1.0 / (1.0 + 0.01 * 0.01));
    const float nC05_rx = -(c05 * i_rx), nCfl_rx = -(cfl * i_rx), nH6_rx = -(h6 * i_rx);
    const float nC05_rn = -(c05 * i_rn), nCfl_rn = -(cfl * i_rn), nH6_rn = -(h6 * i_rn);

    // -------- static per-cell constants, packed (registers, whole run) --------
    float cB[3][SW], cS[3][SW], cCL[SW], cDg[SW];
    float pmw[SW], m0x[SW];
    int anyp = 0;
    #pragma unroll
    for (int j = 0; j < SW; j++) {
        int gj = live ? gx*NYg + (gyb + j) : 0;
        float ms = Msat[gj];
        cCL[j] = (TWO_A / ms) * INV_DX2;
        cDg[j] = MU0f * ms;
        cB[0][j] = Bext[0*NG + gj]; cB[1][j] = Bext[1*NG + gj]; cB[2][j] = Bext[2*NG + gj];
        cS[0][j] = src [0*NG + gj]; cS[1][j] = src [1*NG + gj]; cS[2][j] = src [2*NG + gj];
        float pv = sint ? pmask[gj] : 0.f;
        pmw[j] = pv * ms;
        m0x[j] = 0.f;
        if (pv != 0.f) anyp = 1;
    }
    const u64 rB0 = f2pk(cB[0][0], cB[0][1]);
    const u64 rB1 = f2pk(cB[1][0], cB[1][1]);
    const u64 rB2 = f2pk(cB[2][0], cB[2][1]);
    const u64 rS0 = f2pk(cS[0][0], cS[0][1]);
    const u64 rS1 = f2pk(cS[1][0], cS[1][1]);
    const u64 rS2 = f2pk(cS[2][0], cS[2][1]);
    const u64 rCL2 = f2pk(cCL[0], cCL[1]);
    const u64 nDg2 = f2pk(-cDg[0], -cDg[1]);
    const u64 neg4 = f2pk(-4.f, -4.f);
    const u64 one2 = f2pk(1.f, 1.f);
    const u64 two2 = f2pk(2.f, 2.f);
    const u64 al_rx2 = f2pk(0.5f, 0.5f),  al_rn2 = f2pk(0.01f, 0.01f);
    const u64 nC05x2 = f2pk(nC05_rx, nC05_rx), nC05n2 = f2pk(nC05_rn, nC05_rn);
    const u64 nCflx2 = f2pk(nCfl_rx, nCfl_rx), nCfln2 = f2pk(nCfl_rn, nCfl_rn);
    const u64 nH6x2  = f2pk(nH6_rx, nH6_rx),   nH6n2  = f2pk(nH6_rn, nH6_rn);

    for (int i = tid; i < TSTEPS; i += NT) s_sig[i] = sig[i];
    if (cta0) {
        for (int i = tid; i < TSTEPS; i += NT) out[i] = 0.f;
        if (tid == 0)
            asm volatile("st.relaxed.gpu.u32 [%0], %1;" :: "l"(&g_count), "r"(0u) : "memory");
    }

    const int hasp = __syncthreads_or(anyp);
    if (hasp) {
        float s = 0.f;
        for (int i = tid; i < NG; i += NT) s += pmask[i];
        #pragma unroll
        for (int o = 16; o; o >>= 1) s += __shfl_down_sync(0xffffffffu, s, o);
        if ((tid & 31) == 0) red[tid >> 5] = s;
        __syncthreads();
        if (tid < 32) {
            float v = (tid < NT/32) ? red[tid] : 0.f;
            #pragma unroll
            for (int o = 8; o; o >>= 1) v += __shfl_down_sync(0xffffffffu, v, o);
            if (tid == 0) s_pminv = 1.f / v;
        }
    }

    unsigned lsense = 0;
    initbar(lsense);
    initbar(lsense);

    // m carried packed in registers; SA = step-start state
    u64 mb0 = f2pk(0.f, 0.f), mb1 = f2pk(0.f, 0.f), mb2 = f2pk(1.f, 1.f);
    if (live) {
        *(u64*)&SA[0][e] = mb0;
        *(u64*)&SA[1][e] = mb1;
        *(u64*)&SA[2][e] = mb2;
    }
    __syncthreads();

    for (int step = 0; step < NSTEPS; ++step) {
        const bool  probe = (step >= RELAX);
        const float sv    = probe ? s_sig[step - RELAX] : 0.f;
        const u64   al2   = probe ? al_rn2 : al_rx2;
        const u64   nC05  = probe ? nC05n2 : nC05x2;
        const u64   nCfl  = probe ? nCfln2 : nCflx2;
        const u64   nH62  = probe ? nH6n2  : nH6x2;
        const float* __restrict__ m_in  = g_m[(step + 1) & 1];
        float*       __restrict__ m_out = g_m[step & 1];

        // ---- halo refresh from L2 ----
        if (live && !sint && step > 0) {
            float2 a = __ldcg((const float2*)&m_in[0*NG + g]);
            float2 b = __ldcg((const float2*)&m_in[1*NG + g]);
            float2 c = __ldcg((const float2*)&m_in[2*NG + g]);
            mb0 = f2pk(a.x, a.y); mb1 = f2pk(b.x, b.y); mb2 = f2pk(c.x, c.y);
            *(u64*)&SA[0][e] = mb0; *(u64*)&SA[1][e] = mb1; *(u64*)&SA[2][e] = mb2;
        }

        const u64 sv2 = f2pk(sv, sv);
        const u64 tB0 = f2fma(sv2, rS0, rB0);
        const u64 tB1 = f2fma(sv2, rS1, rB1);
        const u64 tB2 = f2fma(sv2, rS2, rB2);
        u64 st0 = mb0, st1 = mb1, st2 = mb2;
        u64 ac0 = 0, ac1 = 0, ac2 = 0;   // packed +0.0
        __syncthreads();

        // one RK substage, packed f32x2; k' = p + alpha*q
        auto stage = [&](const float (*__restrict__ S)[EXT],
                         float (*__restrict__ D)[EXT],
                         u64 nCoef2, u64 w2, bool writeD) {
            u64 xm0 = *(const u64*)&S[0][emb];
            u64 xm1 = *(const u64*)&S[1][emb];
            u64 xm2 = *(const u64*)&S[2][emb];
            u64 xp0 = *(const u64*)&S[0][epb];
            u64 xp1 = *(const u64*)&S[1][epb];
            u64 xp2 = *(const u64*)&S[2][epb];
            float lf0 = S[0][yL], lf1 = S[1][yL], lf2 = S[2][yL];
            float rg0 = S[0][yR], rg1 = S[1][yR], rg2 = S[2][yR];
            float s0l, s0h, s1l, s1h, s2l, s2h;
            f2up(st0, s0l, s0h); f2up(st1, s1l, s1h); f2up(st2, s2l, s2h);
            u64 yl0 = f2pk(lf0, s0l), yr0 = f2pk(s0h, rg0);
            u64 yl1 = f2pk(lf1, s1l), yr1 = f2pk(s1h, rg1);
            u64 yl2 = f2pk(lf2, s2l), yr2 = f2pk(s2h, rg2);
            u64 l0 = f2fma(neg4, st0, f2add(f2add(xm0, xp0), f2add(yl0, yr0)));
            u64 l1 = f2fma(neg4, st1, f2add(f2add(xm1, xp1), f2add(yl1, yr1)));
            u64 l2 = f2fma(neg4, st2, f2add(f2add(xm2, xp2), f2add(yl2, yr2)));
            u64 Bx = f2fma(rCL2, l0, tB0);
            u64 By = f2fma(rCL2, l1, tB1);
            u64 Bz = f2fma(nDg2, st2, f2fma(rCL2, l2, tB2));
            u64 n0 = f2neg(st0), n1 = f2neg(st1), n2 = f2neg(st2);
            u64 px = f2fma(st1, Bz, f2mul(n2, By));
            u64 py = f2fma(st2, Bx, f2mul(n0, Bz));
            u64 pz = f2fma(st0, By, f2mul(n1, Bx));
            u64 qx = f2fma(st1, pz, f2mul(n2, py));
            u64 qy = f2fma(st2, px, f2mul(n0, pz));
            u64 qz = f2fma(st0, py, f2mul(n1, px));
            u64 k0 = f2fma(al2, qx, px);
            u64 k1 = f2fma(al2, qy, py);
            u64 k2 = f2fma(al2, qz, pz);
            ac0 = f2fma(w2, k0, ac0);
            ac1 = f2fma(w2, k1, ac1);
            ac2 = f2fma(w2, k2, ac2);
            st0 = f2fma(nCoef2, k0, mb0);
            st1 = f2fma(nCoef2, k1, mb1);
            st2 = f2fma(nCoef2, k2, mb2);
            if (writeD) {
                *(u64*)&D[0][e] = st0;
                *(u64*)&D[1][e] = st1;
                *(u64*)&D[2][e] = st2;
            }
        };

        if (scap >= 1) stage(SA, SB, nC05, one2, true);
        __syncthreads();
        if (scap >= 2) stage(SB, SA, nC05, two2, true);
        __syncthreads();
        if (scap >= 3) stage(SA, SB, nCfl, two2, true);
        __syncthreads();
        if (scap >= 4) stage(SB, SA, 0, one2, false);   // k4 folded into acc

        // ---- final m (interior): SA publish + exchange ring to L2 ----
        float part = 0.f;
        if (sint) {
            mb0 = f2fma(nH62, ac0, mb0);
            mb1 = f2fma(nH62, ac1, mb1);
            mb2 = f2fma(nH62, ac2, mb2);
            float v0l, v0h, v1l, v1h, v2l, v2h;
            f2up(mb0, v0l, v0h); f2up(mb1, v1l, v1h); f2up(mb2, v2l, v2h);
            if (step == RELAX - 1) { m0x[0] = v0l; m0x[1] = v0h; }
            if (probe) part = (v0l - m0x[0]) * pmw[0] + (v0h - m0x[1]) * pmw[1];
            *(u64*)&SA[0][e] = mb0; *(u64*)&SA[1][e] = mb1; *(u64*)&SA[2][e] = mb2;
            if (ring) {
                __stcg((float2*)&m_out[0*NG + g], make_float2(v0l, v0h));
                __stcg((float2*)&m_out[1*NG + g], make_float2(v1l, v1h));
                __stcg((float2*)&m_out[2*NG + g], make_float2(v2l, v2h));
            }
        }

        if (step == NSTEPS - 1) {
            if (probe && hasp) {
                #pragma unroll
                for (int o = 16; o; o >>= 1) part += __shfl_down_sync(0xffffffffu, part, o);
                if ((tid & 31) == 0) red[tid >> 5] = part;
                __syncthreads();
                if (tid < 32) {
                    float v2 = (tid < NT/32) ? red[tid] : 0.f;
                    #pragma unroll
                    for (int o = 8; o; o >>= 1) v2 += __shfl_down_sync(0xffffffffu, v2, o);
                    if (tid == 0) atomicAdd(&out[step - RELAX], v2 * s_pminv);
                }
            }
            break;
        }

        // ---- arrive: fire-and-forget, orders prior ring stores ----
        __syncthreads();
        if (tid == 0)
            asm volatile("red.add.release.gpu.u32 [%0], %1;"
                         :: "l"(&g_count), "r"(1u) : "memory");

        // ---- probe reduction overlaps other CTAs' spin ----
        if (probe && hasp) {
            #pragma unroll
            for (int o = 16; o; o >>= 1) part += __shfl_down_sync(0xffffffffu, part, o);
            if ((tid & 31) == 0) red[tid >> 5] = part;
            __syncthreads();
            if (tid < 32) {
                float v2 = (tid < NT/32) ? red[tid] : 0.f;
                #pragma unroll
                for (int o = 8; o; o >>= 1) v2 += __shfl_down_sync(0xffffffffu, v2, o);
                if (tid == 0) atomicAdd(&out[step - RELAX], v2 * s_pminv);
            }
        }

        // ---- wait: ONLY tid0 polls (128 pollers grid-wide), then broadcast ----
        if (tid == 0) {
            const unsigned need = (unsigned)(step + 1) * (unsigned)NCTA;
            unsigned v;
            do {
                asm volatile("ld.acquire.gpu.u32 %0, [%1];" : "=r"(v) : "l"(&g_count) : "memory");
            } while (v < need);
        }
        __syncthreads();
    }
}

// ---------------- host launcher: ONE graph node ----------------
extern "C" void kernel_launch(void* const* d_in, const int* in_sizes, int n_in,
                              void* d_out, int out_size)
{
    const float* sig   = (const float*)d_in[0];
    const float* Bext  = (const float*)d_in[1];
    const float* Msat  = (const float*)d_in[2];
    const float* src   = (const float*)d_in[3];
    const float* pmask = (const float*)d_in[4];
    float* out = (float*)d_out;

    dim3 grid(NBX, NBY);
    k_sim<<<grid, NT>>>(sig, Bext, Msat, src, pmask, out);
}